// round 7
// baseline (speedup 1.0000x reference)
#include <cuda_runtime.h>

// ---------------------------------------------------------------------------
// XNOR-net CNN forward, GB300. Binary convs computed exactly via bitpack +
// popcount (integer-exact vs reference). All smem traffic is 128-bit (uint4).
// Intermediates are 1-bit tensors in __device__ globals (no allocations).
// ---------------------------------------------------------------------------

// Bit tensors: layout [b][y][x][cw], bit j of word cw = channel cw*32+j (1 = positive)
__device__ __align__(16) unsigned g_bits1[128 * 32 * 32 * 4];   // conv1 out signs (128 ch)
__device__ __align__(16) unsigned g_bits2[128 * 16 * 16 * 4];   // after conv2+pool+bn (128 ch)
__device__ __align__(16) unsigned g_bits3[128 * 16 * 16 * 8];   // after conv3+bn (256 ch)
__device__ __align__(16) unsigned g_bits4[128 * 8 * 8 * 8];     // after conv4+pool+bn (256 ch)
__device__ __align__(16) unsigned g_bits5[128 * 8 * 8 * 16];    // after conv5+bn (512 ch)
__device__ float g_h6[128 * 4 * 4 * 512];                       // after conv6+pool+bn (float)

// Packed weights: layout [tap(9)][cin_word][cout], bit j = cin cw*32+j
__device__ unsigned g_pw2[9 * 4 * 128];
__device__ unsigned g_pw3[9 * 4 * 256];
__device__ unsigned g_pw4[9 * 8 * 256];
__device__ unsigned g_pw5[9 * 8 * 512];
__device__ unsigned g_pw6[9 * 16 * 512];

// ---------------------------------------------------------------------------
// Weight bit-packing, all 5 layers in ONE launch. w is HWIO float [3][3][Cin][Cout]
// ---------------------------------------------------------------------------
__device__ __forceinline__ void pack_one(const float* __restrict__ w, unsigned* out,
                                         int Cin, int Cout, int rel)
{
    int co = rel % Cout;
    int q = rel / Cout;            // q = t*cwn + cw
    int cwn = Cin >> 5;
    int cw = q % cwn;
    int t = q / cwn;
    unsigned word = 0;
#pragma unroll 8
    for (int j = 0; j < 32; j++) {
        float v = w[(t * Cin + cw * 32 + j) * Cout + co];
        word |= (v > 0.f ? 1u : 0u) << j;
    }
    out[q * Cout + co] = word;
}

__global__ void __launch_bounds__(256) pack_all_kernel(
    const float* __restrict__ w2, const float* __restrict__ w3,
    const float* __restrict__ w4, const float* __restrict__ w5,
    const float* __restrict__ w6)
{
    int idx = blockIdx.x * 256 + threadIdx.x;
    // ranges: [0,4608) w2, [4608,13824) w3, [13824,32256) w4,
    //         [32256,69120) w5, [69120,142848) w6
    if (idx < 4608)        pack_one(w2, g_pw2, 128, 128, idx);
    else if (idx < 13824)  pack_one(w3, g_pw3, 128, 256, idx - 4608);
    else if (idx < 32256)  pack_one(w4, g_pw4, 256, 256, idx - 13824);
    else if (idx < 69120)  pack_one(w5, g_pw5, 256, 512, idx - 32256);
    else if (idx < 142848) pack_one(w6, g_pw6, 512, 512, idx - 69120);
}

// ---------------------------------------------------------------------------
// conv1: fp32 3x3 conv 3->128 SAME, +b1, relu, BN, sign -> bitpack
// One thread per pixel, computes all 128 output channels in 4x32 chunks.
// ---------------------------------------------------------------------------
__global__ void __launch_bounds__(128) conv1_kernel(
    const float* __restrict__ x, const float* __restrict__ w1,
    const float* __restrict__ b1, const float* __restrict__ s1,
    const float* __restrict__ bi1)
{
    __shared__ __align__(16) float sw[27 * 128];
    __shared__ float sb[128], ss[128], sbi[128];
    int tid = threadIdx.x;
    for (int i = tid; i < 27 * 128; i += 128) sw[i] = w1[i]; // same flat layout
    sb[tid] = b1[tid];
    ss[tid] = s1[tid];
    sbi[tid] = bi1[tid];
    __syncthreads();

    int pid = blockIdx.x * 128 + tid;      // 0..131071
    int b = pid >> 10;
    int y = (pid >> 5) & 31;
    int xx = pid & 31;

    float in[27];
#pragma unroll
    for (int dy = 0; dy < 3; dy++)
#pragma unroll
        for (int dx = 0; dx < 3; dx++) {
            int iy = y + dy - 1, ix = xx + dx - 1;
            bool v = (iy >= 0 && iy < 32 && ix >= 0 && ix < 32);
            const float* p = x + ((b * 32 + iy) * 32 + ix) * 3;
#pragma unroll
            for (int c = 0; c < 3; c++)
                in[(dy * 3 + dx) * 3 + c] = v ? p[c] : 0.f;
        }

#pragma unroll
    for (int chunk = 0; chunk < 4; chunk++) {
        unsigned word = 0;
#pragma unroll
        for (int jj = 0; jj < 8; jj++) {
            int co4 = chunk * 32 + jj * 4;
            float4 acc = make_float4(0.f, 0.f, 0.f, 0.f);
#pragma unroll
            for (int k = 0; k < 27; k++) {
                float4 wv = *reinterpret_cast<const float4*>(&sw[k * 128 + co4]);
                float iv = in[k];
                acc.x = fmaf(iv, wv.x, acc.x);
                acc.y = fmaf(iv, wv.y, acc.y);
                acc.z = fmaf(iv, wv.z, acc.z);
                acc.w = fmaf(iv, wv.w, acc.w);
            }
            float av[4] = {acc.x, acc.y, acc.z, acc.w};
#pragma unroll
            for (int e = 0; e < 4; e++) {
                int co = co4 + e;
                float v = fmaxf(av[e] + sb[co], 0.f);
                bool bit = fmaf(v, ss[co], sbi[co]) > 0.f;
                word |= (bit ? 1u : 0u) << (jj * 4 + e);
            }
        }
        g_bits1[pid * 4 + chunk] = word;
    }
}

// ---------------------------------------------------------------------------
// Binary conv: xnor-popcount with zero halo + weight-sign border correction.
// Warp = 32 consecutive output channels (lane = co). 8 warps split pixels.
// All shared-memory accesses are 128-bit vectorized.
// ---------------------------------------------------------------------------
__device__ __forceinline__ int border_corr(int y, int x, int H, int W, const int S[9])
{
    int c = 0;
    if (y == 0)      c += S[0] + S[1] + S[2];
    if (y == H - 1)  c += S[6] + S[7] + S[8];
    if (x == 0) {
        c += S[0] + S[3] + S[6];
        if (y == 0)     c -= S[0];
        if (y == H - 1) c -= S[6];
    }
    if (x == W - 1) {
        c += S[2] + S[5] + S[8];
        if (y == 0)     c -= S[2];
        if (y == H - 1) c -= S[8];
    }
    return c;
}

__device__ __forceinline__ int popc4x(uint4 a, uint4 w)
{
    return __popc(a.x ^ w.x) + __popc(a.y ^ w.y) + __popc(a.z ^ w.z) + __popc(a.w ^ w.w);
}

template <int H, int W, int CW, int COUT, bool POOL, int LAYER, int NB>
__global__ void __launch_bounds__(256) bconv_kernel(
    const float* __restrict__ bn_s, const float* __restrict__ bn_b)
{
    constexpr int CIN = CW * 32;
    constexpr int OH = POOL ? H / 2 : H;
    constexpr int OW = POOL ? W / 2 : W;
    constexpr int COW = COUT / 32;
    constexpr int G = CW / 4;               // uint4 groups per pixel
    constexpr int HP = (H + 2) * (W + 2);   // halo pixels
    constexpr bool FINAL = (LAYER == 6);

    const unsigned* in_bits;
    const unsigned* wp;
    unsigned* outb = nullptr;
    if constexpr (LAYER == 2) { in_bits = g_bits1; wp = g_pw2; outb = g_bits2; }
    else if constexpr (LAYER == 3) { in_bits = g_bits2; wp = g_pw3; outb = g_bits3; }
    else if constexpr (LAYER == 4) { in_bits = g_bits3; wp = g_pw4; outb = g_bits4; }
    else if constexpr (LAYER == 5) { in_bits = g_bits4; wp = g_pw5; outb = g_bits5; }
    else { in_bits = g_bits5; wp = g_pw6; }

    __shared__ __align__(16) unsigned act[NB * HP * CW];
    // weight smem layout: [t][g][lane][4]  -> lane's 4 cin-words contiguous (LDS.128)
    __shared__ __align__(16) unsigned wsm[9 * CW * 32];

    const int tid = threadIdx.x, lane = tid & 31, warp = tid >> 5;
    const int cog = blockIdx.x;
    const int co = cog * 32 + lane;

    // --- activation bits -> smem with zero halo (uint4 granularity) ---
    {
        uint4* act4w = reinterpret_cast<uint4*>(act);
        const uint4* in4 = reinterpret_cast<const uint4*>(in_bits);
        for (int i = tid; i < NB * HP * G; i += 256) {
            int g = i % G;
            int q = i / G;
            int pix = q % HP;
            int bb = q / HP;
            int xx = pix % (W + 2);
            int yy = pix / (W + 2);
            uint4 v = make_uint4(0u, 0u, 0u, 0u);
            if (yy >= 1 && yy <= H && xx >= 1 && xx <= W)
                v = in4[(((blockIdx.y * NB + bb) * H + (yy - 1)) * W + (xx - 1)) * G + g];
            act4w[i] = v;
        }
    }
    // --- weight bits for this block's 32 output channels (vectorized layout) ---
    for (int i = tid; i < 9 * CW * 32; i += 256) {
        int k = i & 3;
        int l = (i >> 2) & 31;
        int q = i >> 7;                     // q = t*G + g
        int g = q % G, t = q / G;
        int cw = g * 4 + k;
        wsm[i] = wp[(t * CW + cw) * COUT + cog * 32 + l];
    }
    __syncthreads();

    const uint4* act4 = reinterpret_cast<const uint4*>(act);
    const uint4* ws4 = reinterpret_cast<const uint4*>(wsm);

    // per-tap weight sign sums (for border correction)
    int S[9];
#pragma unroll
    for (int t = 0; t < 9; t++) {
        int p = 0;
#pragma unroll
        for (int g = 0; g < G; g++) {
            uint4 w = ws4[(t * G + g) * 32 + lane];
            p += __popc(w.x) + __popc(w.y) + __popc(w.z) + __popc(w.w);
        }
        S[t] = CIN - 2 * p;
    }
    const float scale = bn_s[co], bias = bn_b[co];

    for (int op = warp; op < NB * OH * OW; op += 8) {
        const int bb = op / (OH * OW);
        const int pp = op % (OH * OW);
        const int oy = pp / OW, ox = pp % OW;
        const int b = blockIdx.y * NB + bb;
        const uint4* A = act4 + bb * HP * G;

        if constexpr (POOL) {
            int acc0 = 0, acc1 = 0, acc2 = 0, acc3 = 0;
            const int iy = 2 * oy, ix = 2 * ox;  // halo-space base row/col
#pragma unroll
            for (int g = 0; g < G; g++) {
                uint4 wv[9];
#pragma unroll
                for (int t = 0; t < 9; t++) wv[t] = ws4[(t * G + g) * 32 + lane];
                uint4 a[16];
#pragma unroll
                for (int r = 0; r < 4; r++)
#pragma unroll
                    for (int c = 0; c < 4; c++)
                        a[r * 4 + c] = A[((iy + r) * (W + 2) + (ix + c)) * G + g];
#pragma unroll
                for (int dy = 0; dy < 3; dy++)
#pragma unroll
                    for (int dx = 0; dx < 3; dx++) {
                        const uint4 w = wv[dy * 3 + dx];
                        acc0 += popc4x(a[dy * 4 + dx], w);
                        acc1 += popc4x(a[dy * 4 + dx + 1], w);
                        acc2 += popc4x(a[(dy + 1) * 4 + dx], w);
                        acc3 += popc4x(a[(dy + 1) * 4 + dx + 1], w);
                    }
            }
            int s0 = 9 * CIN - 2 * acc0 - border_corr(2 * oy, 2 * ox, H, W, S);
            int s1 = 9 * CIN - 2 * acc1 - border_corr(2 * oy, 2 * ox + 1, H, W, S);
            int s2 = 9 * CIN - 2 * acc2 - border_corr(2 * oy + 1, 2 * ox, H, W, S);
            int s3 = 9 * CIN - 2 * acc3 - border_corr(2 * oy + 1, 2 * ox + 1, H, W, S);
            int m = max(0, max(max(s0, s1), max(s2, s3)));  // relu then maxpool
            if constexpr (FINAL) {
                g_h6[((b * OH + oy) * OW + ox) * COUT + co] = fmaf((float)m, scale, bias);
            } else {
                bool bit = fmaf((float)m, scale, bias) > 0.f;
                unsigned wd = __ballot_sync(0xffffffffu, bit);
                if (lane == 0) outb[((b * OH + oy) * OW + ox) * COW + cog] = wd;
            }
        } else {
            int acc = 0;
#pragma unroll
            for (int g = 0; g < G; g++) {
                uint4 wv[9];
#pragma unroll
                for (int t = 0; t < 9; t++) wv[t] = ws4[(t * G + g) * 32 + lane];
                uint4 a[9];
#pragma unroll
                for (int r = 0; r < 3; r++)
#pragma unroll
                    for (int c = 0; c < 3; c++)
                        a[r * 3 + c] = A[((oy + r) * (W + 2) + (ox + c)) * G + g];
#pragma unroll
                for (int t = 0; t < 9; t++) acc += popc4x(a[t], wv[t]);
            }
            int s = 9 * CIN - 2 * acc - border_corr(oy, ox, H, W, S);
            int m = max(s, 0);
            bool bit = fmaf((float)m, scale, bias) > 0.f;
            unsigned wd = __ballot_sync(0xffffffffu, bit);
            if (lane == 0) outb[((b * OH + oy) * OW + ox) * COW + cog] = wd;
        }
    }
}

// ---------------------------------------------------------------------------
// Dense (512->10 on last axis) + bias + softmax. One thread per (b,h,w) row.
// ---------------------------------------------------------------------------
__global__ void __launch_bounds__(128) dense_softmax_kernel(
    const float* __restrict__ dw, const float* __restrict__ db, float* __restrict__ out)
{
    __shared__ float sdw[512 * 10];
    __shared__ float sdb[10];
    int tid = threadIdx.x;
    for (int i = tid; i < 5120; i += 128) sdw[i] = dw[i];
    if (tid < 10) sdb[tid] = db[tid];
    __syncthreads();

    int r = blockIdx.x * 128 + tid;   // 0..2047
    float acc[10];
#pragma unroll
    for (int d = 0; d < 10; d++) acc[d] = sdb[d];
    const float* h = g_h6 + r * 512;
    for (int c = 0; c < 512; c++) {
        float hv = h[c];
#pragma unroll
        for (int d = 0; d < 10; d++) acc[d] = fmaf(hv, sdw[c * 10 + d], acc[d]);
    }
    float m = acc[0];
#pragma unroll
    for (int d = 1; d < 10; d++) m = fmaxf(m, acc[d]);
    float e[10], s = 0.f;
#pragma unroll
    for (int d = 0; d < 10; d++) { e[d] = expf(acc[d] - m); s += e[d]; }
    float inv = 1.f / s;
#pragma unroll
    for (int d = 0; d < 10; d++) out[r * 10 + d] = e[d] * inv;
}

// ---------------------------------------------------------------------------
// Launch. Inputs identified by size (robust to metadata vs signature order).
// ---------------------------------------------------------------------------
extern "C" void kernel_launch(void* const* d_in, const int* in_sizes, int n_in,
                              void* d_out, int out_size)
{
    const float *x = nullptr, *w1 = nullptr, *b1 = nullptr;
    const float *w2 = nullptr, *w3 = nullptr, *w4 = nullptr, *w5 = nullptr, *w6 = nullptr;
    const float *dw = nullptr, *db = nullptr;
    const float* bns[12] = {nullptr};
    int bn_idx = 0;

    for (int i = 0; i < n_in; i++) {
        const float* p = (const float*)d_in[i];
        int s = in_sizes[i];
        if (i == 0)              x = p;
        else if (s == 3456)      w1 = p;
        else if (i == 2)         b1 = p;
        else if (s == 147456)    w2 = p;
        else if (s == 294912)    w3 = p;
        else if (s == 589824)    w4 = p;
        else if (s == 1179648)   w5 = p;
        else if (s == 2359296)   w6 = p;
        else if (s == 5120)      dw = p;
        else if (s == 10)        db = p;
        else if (bn_idx < 12)    bns[bn_idx++] = p;
    }
    const float *bn2s = bns[2], *bn2b = bns[3];
    const float *bn3s = bns[4], *bn3b = bns[5];
    const float *bn4s = bns[6], *bn4b = bns[7];
    const float *bn5s = bns[8], *bn5b = bns[9];
    const float *bn6s = bns[10], *bn6b = bns[11];

    // conv1 (float, independent of packing) then all weight packing in one launch
    conv1_kernel<<<1024, 128>>>(x, w1, b1, bns[0], bns[1]);
    pack_all_kernel<<<(142848 + 255) / 256, 256>>>(w2, w3, w4, w5, w6);

    // binary conv chain  <H, W, CW, COUT, POOL, LAYER, NB>
    bconv_kernel<32, 32, 4, 128, true, 2, 1><<<dim3(4, 128), 256>>>(bn2s, bn2b);
    bconv_kernel<16, 16, 4, 256, false, 3, 1><<<dim3(8, 128), 256>>>(bn3s, bn3b);
    bconv_kernel<16, 16, 8, 256, true, 4, 2><<<dim3(8, 64), 256>>>(bn4s, bn4b);
    bconv_kernel<8, 8, 8, 512, false, 5, 2><<<dim3(16, 64), 256>>>(bn5s, bn5b);
    bconv_kernel<8, 8, 16, 512, true, 6, 4><<<dim3(16, 32), 256>>>(bn6s, bn6b);

    // dense + softmax
    dense_softmax_kernel<<<16, 128>>>(dw, db, (float*)d_out);
    (void)out_size;
}

// round 11
// speedup vs baseline: 1.0472x; 1.0472x over previous
#include <cuda_runtime.h>

// ---------------------------------------------------------------------------
// XNOR-net CNN forward, GB300. Binary convs computed exactly via bitpack +
// popcount (integer-exact vs reference). Weights register-resident where
// possible; activations staged in smem (broadcast LDS). No allocations.
// ---------------------------------------------------------------------------

// Bit tensors: layout [b][y][x][cw], bit j of word cw = channel cw*32+j (1 = positive)
__device__ __align__(16) unsigned g_bits1[128 * 32 * 32 * 4];   // conv1 out signs (128 ch)
__device__ __align__(16) unsigned g_bits2[128 * 16 * 16 * 4];   // after conv2+pool+bn (128 ch)
__device__ __align__(16) unsigned g_bits3[128 * 16 * 16 * 8];   // after conv3+bn (256 ch)
__device__ __align__(16) unsigned g_bits4[128 * 8 * 8 * 8];     // after conv4+pool+bn (256 ch)
__device__ __align__(16) unsigned g_bits5[128 * 8 * 8 * 16];    // after conv5+bn (512 ch)
__device__ float g_h6[128 * 4 * 4 * 512];                       // after conv6+pool+bn (float)

// Packed weights, register-friendly layout:
//   uint4 index [(t*G + g)*COUT + co]  holds cin-words cw = g*4 .. g*4+3 for cout co
__device__ __align__(16) unsigned g_pw2[9 * 4 * 128];
__device__ __align__(16) unsigned g_pw3[9 * 4 * 256];
__device__ __align__(16) unsigned g_pw4[9 * 8 * 256];
__device__ __align__(16) unsigned g_pw5[9 * 8 * 512];
__device__ __align__(16) unsigned g_pw6[9 * 16 * 512];

// ---------------------------------------------------------------------------
// Weight bit-packing, all 5 layers in ONE launch. w is HWIO float [3][3][Cin][Cout]
// ---------------------------------------------------------------------------
__device__ __forceinline__ void pack_one(const float* __restrict__ w, unsigned* out,
                                         int Cin, int Cout, int rel)
{
    int co = rel % Cout;
    int q = rel / Cout;            // q = t*cwn + cw
    int cwn = Cin >> 5;
    int cw = q % cwn;
    int t = q / cwn;
    unsigned word = 0;
#pragma unroll 8
    for (int j = 0; j < 32; j++) {
        float v = w[(t * Cin + cw * 32 + j) * Cout + co];
        word |= (v > 0.f ? 1u : 0u) << j;
    }
    int G = cwn >> 2;
    int g = cw >> 2, k = cw & 3;
    out[((t * G + g) * Cout + co) * 4 + k] = word;
}

__global__ void __launch_bounds__(256) pack_all_kernel(
    const float* __restrict__ w2, const float* __restrict__ w3,
    const float* __restrict__ w4, const float* __restrict__ w5,
    const float* __restrict__ w6)
{
    int idx = blockIdx.x * 256 + threadIdx.x;
    if (idx < 4608)        pack_one(w2, g_pw2, 128, 128, idx);
    else if (idx < 13824)  pack_one(w3, g_pw3, 128, 256, idx - 4608);
    else if (idx < 32256)  pack_one(w4, g_pw4, 256, 256, idx - 13824);
    else if (idx < 69120)  pack_one(w5, g_pw5, 256, 512, idx - 32256);
    else if (idx < 142848) pack_one(w6, g_pw6, 512, 512, idx - 69120);
}

// ---------------------------------------------------------------------------
// conv1: fp32 3x3 conv 3->128 SAME, +b1, relu, BN, sign -> bitpack
// ---------------------------------------------------------------------------
__global__ void __launch_bounds__(128) conv1_kernel(
    const float* __restrict__ x, const float* __restrict__ w1,
    const float* __restrict__ b1, const float* __restrict__ s1,
    const float* __restrict__ bi1)
{
    __shared__ __align__(16) float sw[27 * 128];
    __shared__ float sb[128], ss[128], sbi[128];
    int tid = threadIdx.x;
    for (int i = tid; i < 27 * 128; i += 128) sw[i] = w1[i];
    sb[tid] = b1[tid];
    ss[tid] = s1[tid];
    sbi[tid] = bi1[tid];
    __syncthreads();

    int pid = blockIdx.x * 128 + tid;
    int b = pid >> 10;
    int y = (pid >> 5) & 31;
    int xx = pid & 31;

    float in[27];
#pragma unroll
    for (int dy = 0; dy < 3; dy++)
#pragma unroll
        for (int dx = 0; dx < 3; dx++) {
            int iy = y + dy - 1, ix = xx + dx - 1;
            bool v = (iy >= 0 && iy < 32 && ix >= 0 && ix < 32);
            const float* p = x + ((b * 32 + iy) * 32 + ix) * 3;
#pragma unroll
            for (int c = 0; c < 3; c++)
                in[(dy * 3 + dx) * 3 + c] = v ? p[c] : 0.f;
        }

#pragma unroll
    for (int chunk = 0; chunk < 4; chunk++) {
        unsigned word = 0;
#pragma unroll
        for (int jj = 0; jj < 8; jj++) {
            int co4 = chunk * 32 + jj * 4;
            float4 acc = make_float4(0.f, 0.f, 0.f, 0.f);
#pragma unroll
            for (int k = 0; k < 27; k++) {
                float4 wv = *reinterpret_cast<const float4*>(&sw[k * 128 + co4]);
                float iv = in[k];
                acc.x = fmaf(iv, wv.x, acc.x);
                acc.y = fmaf(iv, wv.y, acc.y);
                acc.z = fmaf(iv, wv.z, acc.z);
                acc.w = fmaf(iv, wv.w, acc.w);
            }
            float av[4] = {acc.x, acc.y, acc.z, acc.w};
#pragma unroll
            for (int e = 0; e < 4; e++) {
                int co = co4 + e;
                float v = fmaxf(av[e] + sb[co], 0.f);
                bool bit = fmaf(v, ss[co], sbi[co]) > 0.f;
                word |= (bit ? 1u : 0u) << (jj * 4 + e);
            }
        }
        g_bits1[pid * 4 + chunk] = word;
    }
}

// ---------------------------------------------------------------------------
// Common helpers
// ---------------------------------------------------------------------------
__device__ __forceinline__ int border_corr(int y, int x, int H, int W, const int S[9])
{
    int c = 0;
    if (y == 0)      c += S[0] + S[1] + S[2];
    if (y == H - 1)  c += S[6] + S[7] + S[8];
    if (x == 0) {
        c += S[0] + S[3] + S[6];
        if (y == 0)     c -= S[0];
        if (y == H - 1) c -= S[6];
    }
    if (x == W - 1) {
        c += S[2] + S[5] + S[8];
        if (y == 0)     c -= S[2];
        if (y == H - 1) c -= S[8];
    }
    return c;
}

__device__ __forceinline__ int popc4x(uint4 a, uint4 w)
{
    return __popc(a.x ^ w.x) + __popc(a.y ^ w.y) + __popc(a.z ^ w.z) + __popc(a.w ^ w.w);
}

template <int HP_G>
__device__ __forceinline__ void fill_act(unsigned* act, const unsigned* in_bits,
                                         int base_img, int H, int W, int G,
                                         int tid, int nthreads, int nb)
{
    uint4* act4w = reinterpret_cast<uint4*>(act);
    const uint4* in4 = reinterpret_cast<const uint4*>(in_bits);
    int HP = (H + 2) * (W + 2);
    for (int i = tid; i < nb * HP * G; i += nthreads) {
        int g = i % G;
        int q = i / G;
        int pix = q % HP;
        int bb = q / HP;
        int xx = pix % (W + 2);
        int yy = pix / (W + 2);
        uint4 v = make_uint4(0u, 0u, 0u, 0u);
        if (yy >= 1 && yy <= H && xx >= 1 && xx <= W)
            v = in4[(((base_img + bb) * H + (yy - 1)) * W + (xx - 1)) * G + g];
        act4w[i] = v;
    }
}

// ---------------------------------------------------------------------------
// Non-pool binary conv (L3, L5): weights register-resident, 4 acc chains.
// 128 threads (4 warps), warp = 32 couts (lane = co), warps split pixels.
// ---------------------------------------------------------------------------
template <int H, int W, int CW, int COUT, int LAYER>
__global__ void __launch_bounds__(128) bconv_np_kernel(
    const float* __restrict__ bn_s, const float* __restrict__ bn_b)
{
    constexpr int CIN = CW * 32;
    constexpr int G = CW / 4;
    constexpr int COW = COUT / 32;

    const unsigned* in_bits;
    const unsigned* wp;
    unsigned* outb;
    if constexpr (LAYER == 3) { in_bits = g_bits2; wp = g_pw3; outb = g_bits3; }
    else { in_bits = g_bits4; wp = g_pw5; outb = g_bits5; }

    __shared__ __align__(16) unsigned act[(H + 2) * (W + 2) * CW];

    const int tid = threadIdx.x, lane = tid & 31, warp = tid >> 5;
    const int cog = blockIdx.x, b = blockIdx.y;
    const int co = cog * 32 + lane;

    fill_act<(H + 2) * (W + 2) * G>(act, in_bits, b, H, W, G, tid, 128, 1);

    // hoist weights into registers (per-lane LDG.128)
    const uint4* pw4 = reinterpret_cast<const uint4*>(wp);
    uint4 wv[9 * G];
#pragma unroll
    for (int t = 0; t < 9; t++)
#pragma unroll
        for (int g = 0; g < G; g++)
            wv[t * G + g] = pw4[(t * G + g) * COUT + co];

    int S[9];
#pragma unroll
    for (int t = 0; t < 9; t++) {
        int p = 0;
#pragma unroll
        for (int g = 0; g < G; g++) {
            uint4 w = wv[t * G + g];
            p += __popc(w.x) + __popc(w.y) + __popc(w.z) + __popc(w.w);
        }
        S[t] = CIN - 2 * p;
    }
    const float scale = bn_s[co], bias = bn_b[co];
    __syncthreads();

    const uint4* act4 = reinterpret_cast<const uint4*>(act);

    for (int op = warp; op < H * W; op += 4) {
        const int oy = op / W, ox = op % W;
        const uint4* P = act4 + (oy * (W + 2) + ox) * G;
        int a0 = 0, a1 = 0, a2 = 0, a3 = 0;   // 4 independent chains
#pragma unroll
        for (int g = 0; g < G; g++) {
            uint4 a[9];
#pragma unroll
            for (int r = 0; r < 3; r++)
#pragma unroll
                for (int c = 0; c < 3; c++)
                    a[r * 3 + c] = P[(r * (W + 2) + c) * G + g];
            a0 += popc4x(a[0], wv[0 * G + g]);
            a1 += popc4x(a[1], wv[1 * G + g]);
            a2 += popc4x(a[2], wv[2 * G + g]);
            a3 += popc4x(a[3], wv[3 * G + g]);
            a0 += popc4x(a[4], wv[4 * G + g]);
            a1 += popc4x(a[5], wv[5 * G + g]);
            a2 += popc4x(a[6], wv[6 * G + g]);
            a3 += popc4x(a[7], wv[7 * G + g]);
            a0 += popc4x(a[8], wv[8 * G + g]);
        }
        int acc = (a0 + a1) + (a2 + a3);
        int s = 9 * CIN - 2 * acc - border_corr(oy, ox, H, W, S);
        int m = max(s, 0);
        bool bit = fmaf((float)m, scale, bias) > 0.f;
        unsigned wd = __ballot_sync(0xffffffffu, bit);
        if (lane == 0) outb[((b * H + oy) * W + ox) * COW + cog] = wd;
    }
}

// ---------------------------------------------------------------------------
// Pool binary conv, weights register-resident (L2: G=1, L4: G=2).
// Row-streaming act window (4 uint4 per g) to contain register pressure.
// 128 threads (4 warps).
// ---------------------------------------------------------------------------
template <int H, int W, int CW, int COUT, int LAYER>
__global__ void __launch_bounds__(128) bconv_pool_wreg_kernel(
    const float* __restrict__ bn_s, const float* __restrict__ bn_b)
{
    constexpr int CIN = CW * 32;
    constexpr int OH = H / 2, OW = W / 2;
    constexpr int G = CW / 4;
    constexpr int COW = COUT / 32;

    const unsigned* in_bits;
    const unsigned* wp;
    unsigned* outb;
    if constexpr (LAYER == 2) { in_bits = g_bits1; wp = g_pw2; outb = g_bits2; }
    else { in_bits = g_bits3; wp = g_pw4; outb = g_bits4; }

    __shared__ __align__(16) unsigned act[(H + 2) * (W + 2) * CW];

    const int tid = threadIdx.x, lane = tid & 31, warp = tid >> 5;
    const int cog = blockIdx.x, b = blockIdx.y;
    const int co = cog * 32 + lane;

    fill_act<(H + 2) * (W + 2) * G>(act, in_bits, b, H, W, G, tid, 128, 1);

    const uint4* pw4 = reinterpret_cast<const uint4*>(wp);
    uint4 wv[9 * G];
#pragma unroll
    for (int t = 0; t < 9; t++)
#pragma unroll
        for (int g = 0; g < G; g++)
            wv[t * G + g] = pw4[(t * G + g) * COUT + co];

    int S[9];
#pragma unroll
    for (int t = 0; t < 9; t++) {
        int p = 0;
#pragma unroll
        for (int g = 0; g < G; g++) {
            uint4 w = wv[t * G + g];
            p += __popc(w.x) + __popc(w.y) + __popc(w.z) + __popc(w.w);
        }
        S[t] = CIN - 2 * p;
    }
    const float scale = bn_s[co], bias = bn_b[co];
    __syncthreads();

    const uint4* act4 = reinterpret_cast<const uint4*>(act);

    for (int op = warp; op < OH * OW; op += 4) {
        const int oy = op / OW, ox = op % OW;
        const int iy = 2 * oy, ix = 2 * ox;   // halo-space base
        int p00 = 0, p01 = 0, p10 = 0, p11 = 0;
#pragma unroll
        for (int g = 0; g < G; g++) {
            const uint4* P = act4 + (iy * (W + 2) + ix) * G + g;
#pragma unroll
            for (int r = 0; r < 4; r++) {
                uint4 a0 = P[(r * (W + 2) + 0) * G];
                uint4 a1 = P[(r * (W + 2) + 1) * G];
                uint4 a2 = P[(r * (W + 2) + 2) * G];
                uint4 a3 = P[(r * (W + 2) + 3) * G];
                if (r < 3) {   // top pair, tap row dy = r
                    uint4 w0 = wv[(r * 3 + 0) * G + g];
                    uint4 w1 = wv[(r * 3 + 1) * G + g];
                    uint4 w2 = wv[(r * 3 + 2) * G + g];
                    p00 += popc4x(a0, w0) + popc4x(a1, w1) + popc4x(a2, w2);
                    p01 += popc4x(a1, w0) + popc4x(a2, w1) + popc4x(a3, w2);
                }
                if (r > 0) {   // bottom pair, tap row dy = r-1
                    uint4 w0 = wv[((r - 1) * 3 + 0) * G + g];
                    uint4 w1 = wv[((r - 1) * 3 + 1) * G + g];
                    uint4 w2 = wv[((r - 1) * 3 + 2) * G + g];
                    p10 += popc4x(a0, w0) + popc4x(a1, w1) + popc4x(a2, w2);
                    p11 += popc4x(a1, w0) + popc4x(a2, w1) + popc4x(a3, w2);
                }
            }
        }
        int s0 = 9 * CIN - 2 * p00 - border_corr(iy,     ix,     H, W, S);
        int s1 = 9 * CIN - 2 * p01 - border_corr(iy,     ix + 1, H, W, S);
        int s2 = 9 * CIN - 2 * p10 - border_corr(iy + 1, ix,     H, W, S);
        int s3 = 9 * CIN - 2 * p11 - border_corr(iy + 1, ix + 1, H, W, S);
        int m = max(0, max(max(s0, s1), max(s2, s3)));
        bool bit = fmaf((float)m, scale, bias) > 0.f;
        unsigned wd = __ballot_sync(0xffffffffu, bit);
        if (lane == 0) outb[((b * OH + oy) * OW + ox) * COW + cog] = wd;
    }
}

// ---------------------------------------------------------------------------
// L6: pool, G=4 -> weights in smem (ALU-bound anyway), float output, NB images.
// 256 threads (8 warps).
// ---------------------------------------------------------------------------
template <int NB>
__global__ void __launch_bounds__(256) bconv6_kernel(
    const float* __restrict__ bn_s, const float* __restrict__ bn_b)
{
    constexpr int H = 8, W = 8, CW = 16, COUT = 512;
    constexpr int CIN = 512;
    constexpr int OH = 4, OW = 4;
    constexpr int G = 4;
    constexpr int HP = (H + 2) * (W + 2);

    __shared__ __align__(16) unsigned act[NB * HP * CW];
    __shared__ __align__(16) uint4 wsm[9 * G * 32];

    const int tid = threadIdx.x, lane = tid & 31, warp = tid >> 5;
    const int cog = blockIdx.x;
    const int co = cog * 32 + lane;

    fill_act<NB * HP * G>(act, g_bits5, blockIdx.y * NB, H, W, G, tid, 256, NB);

    const uint4* pw4 = reinterpret_cast<const uint4*>(g_pw6);
    for (int i = tid; i < 9 * G * 32; i += 256) {
        int l = i & 31, q = i >> 5;          // q = t*G + g
        wsm[i] = pw4[q * COUT + cog * 32 + l];
    }
    __syncthreads();

    int S[9];
#pragma unroll
    for (int t = 0; t < 9; t++) {
        int p = 0;
#pragma unroll
        for (int g = 0; g < G; g++) {
            uint4 w = wsm[(t * G + g) * 32 + lane];
            p += __popc(w.x) + __popc(w.y) + __popc(w.z) + __popc(w.w);
        }
        S[t] = CIN - 2 * p;
    }
    const float scale = bn_s[co], bias = bn_b[co];

    const uint4* act4 = reinterpret_cast<const uint4*>(act);

    for (int op = warp; op < NB * OH * OW; op += 8) {
        const int bb = op / (OH * OW);
        const int pp = op % (OH * OW);
        const int oy = pp / OW, ox = pp % OW;
        const int b = blockIdx.y * NB + bb;
        const int iy = 2 * oy, ix = 2 * ox;
        int p00 = 0, p01 = 0, p10 = 0, p11 = 0;
#pragma unroll
        for (int g = 0; g < G; g++) {
            uint4 wv[9];
#pragma unroll
            for (int t = 0; t < 9; t++) wv[t] = wsm[(t * G + g) * 32 + lane];
            const uint4* P = act4 + (bb * HP + iy * (W + 2) + ix) * G + g;
#pragma unroll
            for (int r = 0; r < 4; r++) {
                uint4 a0 = P[(r * (W + 2) + 0) * G];
                uint4 a1 = P[(r * (W + 2) + 1) * G];
                uint4 a2 = P[(r * (W + 2) + 2) * G];
                uint4 a3 = P[(r * (W + 2) + 3) * G];
                if (r < 3) {
                    p00 += popc4x(a0, wv[r * 3 + 0]) + popc4x(a1, wv[r * 3 + 1]) + popc4x(a2, wv[r * 3 + 2]);
                    p01 += popc4x(a1, wv[r * 3 + 0]) + popc4x(a2, wv[r * 3 + 1]) + popc4x(a3, wv[r * 3 + 2]);
                }
                if (r > 0) {
                    p10 += popc4x(a0, wv[(r - 1) * 3 + 0]) + popc4x(a1, wv[(r - 1) * 3 + 1]) + popc4x(a2, wv[(r - 1) * 3 + 2]);
                    p11 += popc4x(a1, wv[(r - 1) * 3 + 0]) + popc4x(a2, wv[(r - 1) * 3 + 1]) + popc4x(a3, wv[(r - 1) * 3 + 2]);
                }
            }
        }
        int s0 = 9 * CIN - 2 * p00 - border_corr(iy,     ix,     H, W, S);
        int s1 = 9 * CIN - 2 * p01 - border_corr(iy,     ix + 1, H, W, S);
        int s2 = 9 * CIN - 2 * p10 - border_corr(iy + 1, ix,     H, W, S);
        int s3 = 9 * CIN - 2 * p11 - border_corr(iy + 1, ix + 1, H, W, S);
        int m = max(0, max(max(s0, s1), max(s2, s3)));
        g_h6[((b * OH + oy) * OW + ox) * COUT + co] = fmaf((float)m, scale, bias);
    }
}

// ---------------------------------------------------------------------------
// Dense (512->10 on last axis) + bias + softmax. One thread per (b,h,w) row.
// ---------------------------------------------------------------------------
__global__ void __launch_bounds__(128) dense_softmax_kernel(
    const float* __restrict__ dw, const float* __restrict__ db, float* __restrict__ out)
{
    __shared__ float sdw[512 * 10];
    __shared__ float sdb[10];
    int tid = threadIdx.x;
    for (int i = tid; i < 5120; i += 128) sdw[i] = dw[i];
    if (tid < 10) sdb[tid] = db[tid];
    __syncthreads();

    int r = blockIdx.x * 128 + tid;
    float acc[10];
#pragma unroll
    for (int d = 0; d < 10; d++) acc[d] = sdb[d];
    const float* h = g_h6 + r * 512;
    for (int c = 0; c < 512; c++) {
        float hv = h[c];
#pragma unroll
        for (int d = 0; d < 10; d++) acc[d] = fmaf(hv, sdw[c * 10 + d], acc[d]);
    }
    float m = acc[0];
#pragma unroll
    for (int d = 1; d < 10; d++) m = fmaxf(m, acc[d]);
    float e[10], s = 0.f;
#pragma unroll
    for (int d = 0; d < 10; d++) { e[d] = expf(acc[d] - m); s += e[d]; }
    float inv = 1.f / s;
#pragma unroll
    for (int d = 0; d < 10; d++) out[r * 10 + d] = e[d] * inv;
}

// ---------------------------------------------------------------------------
// Launch. Inputs identified by size (robust to metadata vs signature order).
// ---------------------------------------------------------------------------
extern "C" void kernel_launch(void* const* d_in, const int* in_sizes, int n_in,
                              void* d_out, int out_size)
{
    const float *x = nullptr, *w1 = nullptr, *b1 = nullptr;
    const float *w2 = nullptr, *w3 = nullptr, *w4 = nullptr, *w5 = nullptr, *w6 = nullptr;
    const float *dw = nullptr, *db = nullptr;
    const float* bns[12] = {nullptr};
    int bn_idx = 0;

    for (int i = 0; i < n_in; i++) {
        const float* p = (const float*)d_in[i];
        int s = in_sizes[i];
        if (i == 0)              x = p;
        else if (s == 3456)      w1 = p;
        else if (i == 2)         b1 = p;
        else if (s == 147456)    w2 = p;
        else if (s == 294912)    w3 = p;
        else if (s == 589824)    w4 = p;
        else if (s == 1179648)   w5 = p;
        else if (s == 2359296)   w6 = p;
        else if (s == 5120)      dw = p;
        else if (s == 10)        db = p;
        else if (bn_idx < 12)    bns[bn_idx++] = p;
    }
    const float *bn2s = bns[2], *bn2b = bns[3];
    const float *bn3s = bns[4], *bn3b = bns[5];
    const float *bn4s = bns[6], *bn4b = bns[7];
    const float *bn5s = bns[8], *bn5b = bns[9];
    const float *bn6s = bns[10], *bn6b = bns[11];

    conv1_kernel<<<1024, 128>>>(x, w1, b1, bns[0], bns[1]);
    pack_all_kernel<<<(142848 + 255) / 256, 256>>>(w2, w3, w4, w5, w6);

    // binary conv chain
    bconv_pool_wreg_kernel<32, 32, 4, 128, 2><<<dim3(4, 128), 128>>>(bn2s, bn2b);
    bconv_np_kernel<16, 16, 4, 256, 3><<<dim3(8, 128), 128>>>(bn3s, bn3b);
    bconv_pool_wreg_kernel<16, 16, 8, 256, 4><<<dim3(8, 128), 128>>>(bn4s, bn4b);
    bconv_np_kernel<8, 8, 8, 512, 5><<<dim3(16, 128), 128>>>(bn5s, bn5b);
    bconv6_kernel<2><<<dim3(16, 64), 256>>>(bn6s, bn6b);

    dense_softmax_kernel<<<16, 128>>>(dw, db, (float*)d_out);
    (void)out_size;
}

// round 12
// speedup vs baseline: 1.0589x; 1.0112x over previous
#include <cuda_runtime.h>

// ---------------------------------------------------------------------------
// XNOR-net CNN forward, GB300. Binary convs computed exactly via bitpack +
// popcount (integer-exact vs reference). Weights register-resident where
// possible; activations staged in smem (broadcast LDS). No allocations.
// ---------------------------------------------------------------------------

// Bit tensors: layout [b][y][x][cw], bit j of word cw = channel cw*32+j (1 = positive)
__device__ __align__(16) unsigned g_bits1[128 * 32 * 32 * 4];   // conv1 out signs (128 ch)
__device__ __align__(16) unsigned g_bits2[128 * 16 * 16 * 4];   // after conv2+pool+bn (128 ch)
__device__ __align__(16) unsigned g_bits3[128 * 16 * 16 * 8];   // after conv3+bn (256 ch)
__device__ __align__(16) unsigned g_bits4[128 * 8 * 8 * 8];     // after conv4+pool+bn (256 ch)
__device__ __align__(16) unsigned g_bits5[128 * 8 * 8 * 16];    // after conv5+bn (512 ch)
__device__ float g_h6[128 * 4 * 4 * 512];                       // after conv6+pool+bn (float)

// Packed weights, register-friendly layout:
//   uint4 index [(t*G + g)*COUT + co]  holds cin-words cw = g*4 .. g*4+3 for cout co
__device__ __align__(16) unsigned g_pw2[9 * 4 * 128];
__device__ __align__(16) unsigned g_pw3[9 * 4 * 256];
__device__ __align__(16) unsigned g_pw4[9 * 8 * 256];
__device__ __align__(16) unsigned g_pw5[9 * 8 * 512];
__device__ __align__(16) unsigned g_pw6[9 * 16 * 512];

// ---------------------------------------------------------------------------
// Weight bit-packing, all 5 layers in ONE launch. w is HWIO float [3][3][Cin][Cout]
// ---------------------------------------------------------------------------
__device__ __forceinline__ void pack_one(const float* __restrict__ w, unsigned* out,
                                         int Cin, int Cout, int rel)
{
    int co = rel % Cout;
    int q = rel / Cout;            // q = t*cwn + cw
    int cwn = Cin >> 5;
    int cw = q % cwn;
    int t = q / cwn;
    unsigned word = 0;
#pragma unroll 8
    for (int j = 0; j < 32; j++) {
        float v = w[(t * Cin + cw * 32 + j) * Cout + co];
        word |= (v > 0.f ? 1u : 0u) << j;
    }
    int G = cwn >> 2;
    int g = cw >> 2, k = cw & 3;
    out[((t * G + g) * Cout + co) * 4 + k] = word;
}

__global__ void __launch_bounds__(256) pack_all_kernel(
    const float* __restrict__ w2, const float* __restrict__ w3,
    const float* __restrict__ w4, const float* __restrict__ w5,
    const float* __restrict__ w6)
{
    int idx = blockIdx.x * 256 + threadIdx.x;
    if (idx < 4608)        pack_one(w2, g_pw2, 128, 128, idx);
    else if (idx < 13824)  pack_one(w3, g_pw3, 128, 256, idx - 4608);
    else if (idx < 32256)  pack_one(w4, g_pw4, 256, 256, idx - 13824);
    else if (idx < 69120)  pack_one(w5, g_pw5, 256, 512, idx - 32256);
    else if (idx < 142848) pack_one(w6, g_pw6, 512, 512, idx - 69120);
}

// ---------------------------------------------------------------------------
// conv1: fp32 3x3 conv 3->128 SAME, +b1, relu, BN, sign -> bitpack
// ---------------------------------------------------------------------------
__global__ void __launch_bounds__(128) conv1_kernel(
    const float* __restrict__ x, const float* __restrict__ w1,
    const float* __restrict__ b1, const float* __restrict__ s1,
    const float* __restrict__ bi1)
{
    __shared__ __align__(16) float sw[27 * 128];
    __shared__ float sb[128], ss[128], sbi[128];
    int tid = threadIdx.x;
    for (int i = tid; i < 27 * 128; i += 128) sw[i] = w1[i];
    sb[tid] = b1[tid];
    ss[tid] = s1[tid];
    sbi[tid] = bi1[tid];
    __syncthreads();

    int pid = blockIdx.x * 128 + tid;
    int b = pid >> 10;
    int y = (pid >> 5) & 31;
    int xx = pid & 31;

    float in[27];
#pragma unroll
    for (int dy = 0; dy < 3; dy++)
#pragma unroll
        for (int dx = 0; dx < 3; dx++) {
            int iy = y + dy - 1, ix = xx + dx - 1;
            bool v = (iy >= 0 && iy < 32 && ix >= 0 && ix < 32);
            const float* p = x + ((b * 32 + iy) * 32 + ix) * 3;
#pragma unroll
            for (int c = 0; c < 3; c++)
                in[(dy * 3 + dx) * 3 + c] = v ? p[c] : 0.f;
        }

#pragma unroll
    for (int chunk = 0; chunk < 4; chunk++) {
        unsigned word = 0;
#pragma unroll
        for (int jj = 0; jj < 8; jj++) {
            int co4 = chunk * 32 + jj * 4;
            float4 acc = make_float4(0.f, 0.f, 0.f, 0.f);
#pragma unroll
            for (int k = 0; k < 27; k++) {
                float4 wv = *reinterpret_cast<const float4*>(&sw[k * 128 + co4]);
                float iv = in[k];
                acc.x = fmaf(iv, wv.x, acc.x);
                acc.y = fmaf(iv, wv.y, acc.y);
                acc.z = fmaf(iv, wv.z, acc.z);
                acc.w = fmaf(iv, wv.w, acc.w);
            }
            float av[4] = {acc.x, acc.y, acc.z, acc.w};
#pragma unroll
            for (int e = 0; e < 4; e++) {
                int co = co4 + e;
                float v = fmaxf(av[e] + sb[co], 0.f);
                bool bit = fmaf(v, ss[co], sbi[co]) > 0.f;
                word |= (bit ? 1u : 0u) << (jj * 4 + e);
            }
        }
        g_bits1[pid * 4 + chunk] = word;
    }
}

// ---------------------------------------------------------------------------
// Common helpers
// ---------------------------------------------------------------------------
__device__ __forceinline__ int border_corr(int y, int x, int H, int W, const int S[9])
{
    int c = 0;
    if (y == 0)      c += S[0] + S[1] + S[2];
    if (y == H - 1)  c += S[6] + S[7] + S[8];
    if (x == 0) {
        c += S[0] + S[3] + S[6];
        if (y == 0)     c -= S[0];
        if (y == H - 1) c -= S[6];
    }
    if (x == W - 1) {
        c += S[2] + S[5] + S[8];
        if (y == 0)     c -= S[2];
        if (y == H - 1) c -= S[8];
    }
    return c;
}

__device__ __forceinline__ int popc4x(uint4 a, uint4 w)
{
    return __popc(a.x ^ w.x) + __popc(a.y ^ w.y) + __popc(a.z ^ w.z) + __popc(a.w ^ w.w);
}

template <int HP_G>
__device__ __forceinline__ void fill_act(unsigned* act, const unsigned* in_bits,
                                         int base_img, int H, int W, int G,
                                         int tid, int nthreads, int nb)
{
    uint4* act4w = reinterpret_cast<uint4*>(act);
    const uint4* in4 = reinterpret_cast<const uint4*>(in_bits);
    int HP = (H + 2) * (W + 2);
    for (int i = tid; i < nb * HP * G; i += nthreads) {
        int g = i % G;
        int q = i / G;
        int pix = q % HP;
        int bb = q / HP;
        int xx = pix % (W + 2);
        int yy = pix / (W + 2);
        uint4 v = make_uint4(0u, 0u, 0u, 0u);
        if (yy >= 1 && yy <= H && xx >= 1 && xx <= W)
            v = in4[(((base_img + bb) * H + (yy - 1)) * W + (xx - 1)) * G + g];
        act4w[i] = v;
    }
}

// ---------------------------------------------------------------------------
// Non-pool binary conv (L3, L5): weights register-resident, 4 acc chains.
// 128 threads (4 warps), warp = 32 couts (lane = co), warps split pixels.
// ---------------------------------------------------------------------------
template <int H, int W, int CW, int COUT, int LAYER>
__global__ void __launch_bounds__(128) bconv_np_kernel(
    const float* __restrict__ bn_s, const float* __restrict__ bn_b)
{
    constexpr int CIN = CW * 32;
    constexpr int G = CW / 4;
    constexpr int COW = COUT / 32;

    const unsigned* in_bits;
    const unsigned* wp;
    unsigned* outb;
    if constexpr (LAYER == 3) { in_bits = g_bits2; wp = g_pw3; outb = g_bits3; }
    else { in_bits = g_bits4; wp = g_pw5; outb = g_bits5; }

    __shared__ __align__(16) unsigned act[(H + 2) * (W + 2) * CW];

    const int tid = threadIdx.x, lane = tid & 31, warp = tid >> 5;
    const int cog = blockIdx.x, b = blockIdx.y;
    const int co = cog * 32 + lane;

    fill_act<(H + 2) * (W + 2) * G>(act, in_bits, b, H, W, G, tid, 128, 1);

    // hoist weights into registers (per-lane LDG.128)
    const uint4* pw4 = reinterpret_cast<const uint4*>(wp);
    uint4 wv[9 * G];
#pragma unroll
    for (int t = 0; t < 9; t++)
#pragma unroll
        for (int g = 0; g < G; g++)
            wv[t * G + g] = pw4[(t * G + g) * COUT + co];

    int S[9];
#pragma unroll
    for (int t = 0; t < 9; t++) {
        int p = 0;
#pragma unroll
        for (int g = 0; g < G; g++) {
            uint4 w = wv[t * G + g];
            p += __popc(w.x) + __popc(w.y) + __popc(w.z) + __popc(w.w);
        }
        S[t] = CIN - 2 * p;
    }
    const float scale = bn_s[co], bias = bn_b[co];
    __syncthreads();

    const uint4* act4 = reinterpret_cast<const uint4*>(act);

    for (int op = warp; op < H * W; op += 4) {
        const int oy = op / W, ox = op % W;
        const uint4* P = act4 + (oy * (W + 2) + ox) * G;
        int a0 = 0, a1 = 0, a2 = 0, a3 = 0;   // 4 independent chains
#pragma unroll
        for (int g = 0; g < G; g++) {
            uint4 a[9];
#pragma unroll
            for (int r = 0; r < 3; r++)
#pragma unroll
                for (int c = 0; c < 3; c++)
                    a[r * 3 + c] = P[(r * (W + 2) + c) * G + g];
            a0 += popc4x(a[0], wv[0 * G + g]);
            a1 += popc4x(a[1], wv[1 * G + g]);
            a2 += popc4x(a[2], wv[2 * G + g]);
            a3 += popc4x(a[3], wv[3 * G + g]);
            a0 += popc4x(a[4], wv[4 * G + g]);
            a1 += popc4x(a[5], wv[5 * G + g]);
            a2 += popc4x(a[6], wv[6 * G + g]);
            a3 += popc4x(a[7], wv[7 * G + g]);
            a0 += popc4x(a[8], wv[8 * G + g]);
        }
        int acc = (a0 + a1) + (a2 + a3);
        int s = 9 * CIN - 2 * acc - border_corr(oy, ox, H, W, S);
        int m = max(s, 0);
        bool bit = fmaf((float)m, scale, bias) > 0.f;
        unsigned wd = __ballot_sync(0xffffffffu, bit);
        if (lane == 0) outb[((b * H + oy) * W + ox) * COW + cog] = wd;
    }
}

// ---------------------------------------------------------------------------
// Pool binary conv, weights register-resident (L2: G=1, L4: G=2).
// Row-streaming act window (4 uint4 per g) to contain register pressure.
// 128 threads (4 warps).
// ---------------------------------------------------------------------------
template <int H, int W, int CW, int COUT, int LAYER>
__global__ void __launch_bounds__(128) bconv_pool_wreg_kernel(
    const float* __restrict__ bn_s, const float* __restrict__ bn_b)
{
    constexpr int CIN = CW * 32;
    constexpr int OH = H / 2, OW = W / 2;
    constexpr int G = CW / 4;
    constexpr int COW = COUT / 32;

    const unsigned* in_bits;
    const unsigned* wp;
    unsigned* outb;
    if constexpr (LAYER == 2) { in_bits = g_bits1; wp = g_pw2; outb = g_bits2; }
    else { in_bits = g_bits3; wp = g_pw4; outb = g_bits4; }

    __shared__ __align__(16) unsigned act[(H + 2) * (W + 2) * CW];

    const int tid = threadIdx.x, lane = tid & 31, warp = tid >> 5;
    const int cog = blockIdx.x, b = blockIdx.y;
    const int co = cog * 32 + lane;

    fill_act<(H + 2) * (W + 2) * G>(act, in_bits, b, H, W, G, tid, 128, 1);

    const uint4* pw4 = reinterpret_cast<const uint4*>(wp);
    uint4 wv[9 * G];
#pragma unroll
    for (int t = 0; t < 9; t++)
#pragma unroll
        for (int g = 0; g < G; g++)
            wv[t * G + g] = pw4[(t * G + g) * COUT + co];

    int S[9];
#pragma unroll
    for (int t = 0; t < 9; t++) {
        int p = 0;
#pragma unroll
        for (int g = 0; g < G; g++) {
            uint4 w = wv[t * G + g];
            p += __popc(w.x) + __popc(w.y) + __popc(w.z) + __popc(w.w);
        }
        S[t] = CIN - 2 * p;
    }
    const float scale = bn_s[co], bias = bn_b[co];
    __syncthreads();

    const uint4* act4 = reinterpret_cast<const uint4*>(act);

    for (int op = warp; op < OH * OW; op += 4) {
        const int oy = op / OW, ox = op % OW;
        const int iy = 2 * oy, ix = 2 * ox;   // halo-space base
        int p00 = 0, p01 = 0, p10 = 0, p11 = 0;
#pragma unroll
        for (int g = 0; g < G; g++) {
            const uint4* P = act4 + (iy * (W + 2) + ix) * G + g;
#pragma unroll
            for (int r = 0; r < 4; r++) {
                uint4 a0 = P[(r * (W + 2) + 0) * G];
                uint4 a1 = P[(r * (W + 2) + 1) * G];
                uint4 a2 = P[(r * (W + 2) + 2) * G];
                uint4 a3 = P[(r * (W + 2) + 3) * G];
                if (r < 3) {   // top pair, tap row dy = r
                    uint4 w0 = wv[(r * 3 + 0) * G + g];
                    uint4 w1 = wv[(r * 3 + 1) * G + g];
                    uint4 w2 = wv[(r * 3 + 2) * G + g];
                    p00 += popc4x(a0, w0) + popc4x(a1, w1) + popc4x(a2, w2);
                    p01 += popc4x(a1, w0) + popc4x(a2, w1) + popc4x(a3, w2);
                }
                if (r > 0) {   // bottom pair, tap row dy = r-1
                    uint4 w0 = wv[((r - 1) * 3 + 0) * G + g];
                    uint4 w1 = wv[((r - 1) * 3 + 1) * G + g];
                    uint4 w2 = wv[((r - 1) * 3 + 2) * G + g];
                    p10 += popc4x(a0, w0) + popc4x(a1, w1) + popc4x(a2, w2);
                    p11 += popc4x(a1, w0) + popc4x(a2, w1) + popc4x(a3, w2);
                }
            }
        }
        int s0 = 9 * CIN - 2 * p00 - border_corr(iy,     ix,     H, W, S);
        int s1 = 9 * CIN - 2 * p01 - border_corr(iy,     ix + 1, H, W, S);
        int s2 = 9 * CIN - 2 * p10 - border_corr(iy + 1, ix,     H, W, S);
        int s3 = 9 * CIN - 2 * p11 - border_corr(iy + 1, ix + 1, H, W, S);
        int m = max(0, max(max(s0, s1), max(s2, s3)));
        bool bit = fmaf((float)m, scale, bias) > 0.f;
        unsigned wd = __ballot_sync(0xffffffffu, bit);
        if (lane == 0) outb[((b * OH + oy) * OW + ox) * COW + cog] = wd;
    }
}

// ---------------------------------------------------------------------------
// L6: pool, G=4 -> weights in smem (ALU-bound anyway), float output, NB images.
// 256 threads (8 warps).
// ---------------------------------------------------------------------------
template <int NB>
__global__ void __launch_bounds__(256) bconv6_kernel(
    const float* __restrict__ bn_s, const float* __restrict__ bn_b)
{
    constexpr int H = 8, W = 8, CW = 16, COUT = 512;
    constexpr int CIN = 512;
    constexpr int OH = 4, OW = 4;
    constexpr int G = 4;
    constexpr int HP = (H + 2) * (W + 2);

    __shared__ __align__(16) unsigned act[NB * HP * CW];
    __shared__ __align__(16) uint4 wsm[9 * G * 32];

    const int tid = threadIdx.x, lane = tid & 31, warp = tid >> 5;
    const int cog = blockIdx.x;
    const int co = cog * 32 + lane;

    fill_act<NB * HP * G>(act, g_bits5, blockIdx.y * NB, H, W, G, tid, 256, NB);

    const uint4* pw4 = reinterpret_cast<const uint4*>(g_pw6);
    for (int i = tid; i < 9 * G * 32; i += 256) {
        int l = i & 31, q = i >> 5;          // q = t*G + g
        wsm[i] = pw4[q * COUT + cog * 32 + l];
    }
    __syncthreads();

    int S[9];
#pragma unroll
    for (int t = 0; t < 9; t++) {
        int p = 0;
#pragma unroll
        for (int g = 0; g < G; g++) {
            uint4 w = wsm[(t * G + g) * 32 + lane];
            p += __popc(w.x) + __popc(w.y) + __popc(w.z) + __popc(w.w);
        }
        S[t] = CIN - 2 * p;
    }
    const float scale = bn_s[co], bias = bn_b[co];

    const uint4* act4 = reinterpret_cast<const uint4*>(act);

    for (int op = warp; op < NB * OH * OW; op += 8) {
        const int bb = op / (OH * OW);
        const int pp = op % (OH * OW);
        const int oy = pp / OW, ox = pp % OW;
        const int b = blockIdx.y * NB + bb;
        const int iy = 2 * oy, ix = 2 * ox;
        int p00 = 0, p01 = 0, p10 = 0, p11 = 0;
#pragma unroll
        for (int g = 0; g < G; g++) {
            uint4 wv[9];
#pragma unroll
            for (int t = 0; t < 9; t++) wv[t] = wsm[(t * G + g) * 32 + lane];
            const uint4* P = act4 + (bb * HP + iy * (W + 2) + ix) * G + g;
#pragma unroll
            for (int r = 0; r < 4; r++) {
                uint4 a0 = P[(r * (W + 2) + 0) * G];
                uint4 a1 = P[(r * (W + 2) + 1) * G];
                uint4 a2 = P[(r * (W + 2) + 2) * G];
                uint4 a3 = P[(r * (W + 2) + 3) * G];
                if (r < 3) {
                    p00 += popc4x(a0, wv[r * 3 + 0]) + popc4x(a1, wv[r * 3 + 1]) + popc4x(a2, wv[r * 3 + 2]);
                    p01 += popc4x(a1, wv[r * 3 + 0]) + popc4x(a2, wv[r * 3 + 1]) + popc4x(a3, wv[r * 3 + 2]);
                }
                if (r > 0) {
                    p10 += popc4x(a0, wv[(r - 1) * 3 + 0]) + popc4x(a1, wv[(r - 1) * 3 + 1]) + popc4x(a2, wv[(r - 1) * 3 + 2]);
                    p11 += popc4x(a1, wv[(r - 1) * 3 + 0]) + popc4x(a2, wv[(r - 1) * 3 + 1]) + popc4x(a3, wv[(r - 1) * 3 + 2]);
                }
            }
        }
        int s0 = 9 * CIN - 2 * p00 - border_corr(iy,     ix,     H, W, S);
        int s1 = 9 * CIN - 2 * p01 - border_corr(iy,     ix + 1, H, W, S);
        int s2 = 9 * CIN - 2 * p10 - border_corr(iy + 1, ix,     H, W, S);
        int s3 = 9 * CIN - 2 * p11 - border_corr(iy + 1, ix + 1, H, W, S);
        int m = max(0, max(max(s0, s1), max(s2, s3)));
        g_h6[((b * OH + oy) * OW + ox) * COUT + co] = fmaf((float)m, scale, bias);
    }
}

// ---------------------------------------------------------------------------
// Dense (512->10 on last axis) + bias + softmax. One thread per (b,h,w) row.
// ---------------------------------------------------------------------------
__global__ void __launch_bounds__(128) dense_softmax_kernel(
    const float* __restrict__ dw, const float* __restrict__ db, float* __restrict__ out)
{
    __shared__ float sdw[512 * 10];
    __shared__ float sdb[10];
    int tid = threadIdx.x;
    for (int i = tid; i < 5120; i += 128) sdw[i] = dw[i];
    if (tid < 10) sdb[tid] = db[tid];
    __syncthreads();

    int r = blockIdx.x * 128 + tid;
    float acc[10];
#pragma unroll
    for (int d = 0; d < 10; d++) acc[d] = sdb[d];
    const float* h = g_h6 + r * 512;
    for (int c = 0; c < 512; c++) {
        float hv = h[c];
#pragma unroll
        for (int d = 0; d < 10; d++) acc[d] = fmaf(hv, sdw[c * 10 + d], acc[d]);
    }
    float m = acc[0];
#pragma unroll
    for (int d = 1; d < 10; d++) m = fmaxf(m, acc[d]);
    float e[10], s = 0.f;
#pragma unroll
    for (int d = 0; d < 10; d++) { e[d] = expf(acc[d] - m); s += e[d]; }
    float inv = 1.f / s;
#pragma unroll
    for (int d = 0; d < 10; d++) out[r * 10 + d] = e[d] * inv;
}

// ---------------------------------------------------------------------------
// Launch. Inputs identified by size (robust to metadata vs signature order).
// ---------------------------------------------------------------------------
extern "C" void kernel_launch(void* const* d_in, const int* in_sizes, int n_in,
                              void* d_out, int out_size)
{
    const float *x = nullptr, *w1 = nullptr, *b1 = nullptr;
    const float *w2 = nullptr, *w3 = nullptr, *w4 = nullptr, *w5 = nullptr, *w6 = nullptr;
    const float *dw = nullptr, *db = nullptr;
    const float* bns[12] = {nullptr};
    int bn_idx = 0;

    for (int i = 0; i < n_in; i++) {
        const float* p = (const float*)d_in[i];
        int s = in_sizes[i];
        if (i == 0)              x = p;
        else if (s == 3456)      w1 = p;
        else if (i == 2)         b1 = p;
        else if (s == 147456)    w2 = p;
        else if (s == 294912)    w3 = p;
        else if (s == 589824)    w4 = p;
        else if (s == 1179648)   w5 = p;
        else if (s == 2359296)   w6 = p;
        else if (s == 5120)      dw = p;
        else if (s == 10)        db = p;
        else if (bn_idx < 12)    bns[bn_idx++] = p;
    }
    const float *bn2s = bns[2], *bn2b = bns[3];
    const float *bn3s = bns[4], *bn3b = bns[5];
    const float *bn4s = bns[6], *bn4b = bns[7];
    const float *bn5s = bns[8], *bn5b = bns[9];
    const float *bn6s = bns[10], *bn6b = bns[11];

    conv1_kernel<<<1024, 128>>>(x, w1, b1, bns[0], bns[1]);
    pack_all_kernel<<<(142848 + 255) / 256, 256>>>(w2, w3, w4, w5, w6);

    // binary conv chain
    bconv_pool_wreg_kernel<32, 32, 4, 128, 2><<<dim3(4, 128), 128>>>(bn2s, bn2b);
    bconv_np_kernel<16, 16, 4, 256, 3><<<dim3(8, 128), 128>>>(bn3s, bn3b);
    bconv_pool_wreg_kernel<16, 16, 8, 256, 4><<<dim3(8, 128), 128>>>(bn4s, bn4b);
    bconv_np_kernel<8, 8, 8, 512, 5><<<dim3(16, 128), 128>>>(bn5s, bn5b);
    bconv6_kernel<2><<<dim3(16, 64), 256>>>(bn6s, bn6b);

    dense_softmax_kernel<<<16, 128>>>(dw, db, (float*)d_out);
    (void)out_size;
}